// round 16
// baseline (speedup 1.0000x reference)
#include <cuda_runtime.h>

#define YS 256
#define XS 16
#define TS 2048
#define TM1 2047
#define CCH 32       // chunks per recursion (L = 64)
#define NSLOT 3      // ring depth 3
#define WU 15        // warmup steps for interior chunks

// Output packing (float32):
// alpha (T*Y) | beta (T*Y) | p (1) | gamma (T*Y) | xi ((T-1)*Y*Y) | path (T)
#define OFF_ALPHA 0
#define OFF_BETA  (TS * YS)
#define OFF_P     (2 * TS * YS)
#define OFF_GAMMA (2 * TS * YS + 1)
#define OFF_XI    ((size_t)(3 * TS * YS + 1))
#define OFF_PATH  (OFF_XI + (size_t)TM1 * YS * YS)

// Scratch (static device memory)
__device__ float g_bx[TS * YS];
__device__ float g_alpha[TS * YS];       // raw (unscaled) alpha
__device__ float g_beta[TS * YS];        // raw (unscaled) beta
__device__ unsigned char g_bp[TM1 * YS];
__device__ float g_SfA[CCH][2], g_SoA[CCH][2];
__device__ float g_SfB[CCH][2], g_SoB[CCH][2];
__device__ float g_SlA[2];
__device__ float g_kap[CCH], g_lam[CCH];
__device__ float g_p;

// FTZ multiply — matches reference flush-to-zero f32 (bit-verified R6).
__device__ __forceinline__ float fmul_ftz(float a, float b) {
    float r;
    asm("mul.rn.ftz.f32 %0, %1, %2;" : "=f"(r) : "f"(a), "f"(b));
    return r;
}
__device__ __forceinline__ unsigned int smem_u32(const void* p) {
    unsigned int a;
    asm("{ .reg .u64 t; cvta.to.shared.u64 t, %1; cvt.u32.u64 %0, t; }"
        : "=r"(a) : "l"(p));
    return a;
}
__device__ __forceinline__ unsigned int ctarank() {
    unsigned int r;
    asm("mov.u32 %0, %%cluster_ctarank;" : "=r"(r));
    return r;
}
__device__ __forceinline__ void push_quad(unsigned int bufaddr, unsigned int rank,
                                          float4 v) {
    asm volatile(
        "{ .reg .b32 ra;\n\t"
        "mapa.shared::cluster.u32 ra, %0, %1;\n\t"
        "st.shared::cluster.v4.f32 [ra], {%2,%3,%4,%5}; }"
        :: "r"(bufaddr), "r"(rank),
           "f"(v.x), "f"(v.y), "f"(v.z), "f"(v.w) : "memory");
}
__device__ __forceinline__ void push_u32(unsigned int addr, unsigned int rank,
                                         unsigned int v) {
    asm volatile(
        "{ .reg .b32 ra;\n\t"
        "mapa.shared::cluster.u32 ra, %0, %1;\n\t"
        "st.shared::cluster.b32 [ra], %2; }"
        :: "r"(addr), "r"(rank), "r"(v) : "memory");
}
__device__ __forceinline__ void flag_release(unsigned int flagaddr, unsigned int rank,
                                             unsigned int val) {
    asm volatile(
        "{ .reg .b32 rb;\n\t"
        "mapa.shared::cluster.u32 rb, %0, %1;\n\t"
        "st.release.cluster.shared::cluster.b32 [rb], %2; }"
        :: "r"(flagaddr), "r"(rank), "r"(val) : "memory");
}
__device__ __forceinline__ unsigned int ld_rlx(unsigned int addr) {
    unsigned int v;
    asm volatile("ld.relaxed.cluster.shared::cta.b32 %0, [%1];"
                 : "=r"(v) : "r"(addr) : "memory");
    return v;
}
__device__ __forceinline__ unsigned int ld_acq(unsigned int addr) {
    unsigned int v;
    asm volatile("ld.acquire.cluster.shared::cta.b32 %0, [%1];"
                 : "=r"(v) : "r"(addr) : "memory");
    return v;
}
#define CLUSTER_ARRIVE() asm volatile("barrier.cluster.arrive.aligned;" ::: "memory")
#define CLUSTER_WAIT()   asm volatile("barrier.cluster.wait.aligned;" ::: "memory")

// ---------------------------------------------------------------- prep
__global__ void prep_bx_kernel(const int* __restrict__ x,
                               const float* __restrict__ b) {
    int t = blockIdx.x, j = threadIdx.x;
    g_bx[t * YS + j] = b[j * XS + x[t]];
}

// dummies keep chunk_kernel as the 4th launch for ncu capture
__global__ void dummy_kernel() {}

// ---------------------------------------------------------------- chunk kernel
// grid = 130 CTAs = 65 clusters of 2, 512 threads.
// NEW layout: thread owns 4 columns (quad cq = cbase + 4*cg, cg = lane>>4) and
// 16 k-values (k = 16*j + ks, ks = lane&15). Reduction over 16 lanes -> 4-level
// butterfly x 4 floats = 16 SHFL/step (was 40). A-regs still 64 floats.
__global__ void __cluster_dims__(2, 1, 1) __launch_bounds__(512, 1)
chunk_kernel(const float* __restrict__ A,
             const float* __restrict__ pi,
             float* __restrict__ out) {
    __shared__ __align__(16) float s_buf[NSLOT][YS];
    __shared__ __align__(16) unsigned int s_flags[NSLOT][64]; // [slot][srcCTA*32+w*2+cg]
    __shared__ __align__(8) unsigned char s_bpc[64 * YS];     // Viterbi bp cache (rank 0)
    __shared__ float s_redf[32];
    __shared__ unsigned int s_redu[16];
    __shared__ int s_dead, s_last;

    const int tid  = threadIdx.x;
    const int w    = tid >> 5;
    const int lane = tid & 31;
    const int cg   = lane >> 4;          // column-quad group (0/1)
    const int ks   = lane & 15;          // k slice
    const unsigned int r = ctarank();
    const int pair = blockIdx.x >> 1;
    const int mode = (pair == 0) ? 2 : (pair <= CCH ? 0 : 1);
    const int c    = (pair == 0) ? 0 : (pair <= CCH ? pair - 1 : pair - 1 - CCH);
    const int cbase = (int)r * 128 + w * 8;
    const int cq    = cbase + 4 * cg;    // this thread's output quad

    const unsigned int bufu  = smem_u32(&s_buf[0][0]);
    const unsigned int flagu = smem_u32(&s_flags[0][0]);
    const unsigned int bpcu  = smem_u32(&s_bpc[0]);

    if (tid < NSLOT * 64) ((unsigned int*)s_flags)[tid] = 0u;
    if (tid == 0) { s_dead = 0; s_last = 0; }

    // ---- A slice into registers: aq[j] pairs with v[16*j + ks] ----
    float4 aq[16];
    if (mode != 1) {
        // forward: out_c = sum_k v[k] * A[k][c]
#pragma unroll
        for (int j = 0; j < 16; ++j)
            aq[j] = __ldg((const float4*)(A + (size_t)(16 * j + ks) * YS + cq));
    } else {
        // beta: out_c = sum_k A[c][k] * w[k]
#pragma unroll
        for (int j = 0; j < 16; ++j) {
            int k = 16 * j + ks;
            aq[j].x = __ldg(A + (size_t)(cq + 0) * YS + k);
            aq[j].y = __ldg(A + (size_t)(cq + 1) * YS + k);
            aq[j].z = __ldg(A + (size_t)(cq + 2) * YS + k);
            aq[j].w = __ldg(A + (size_t)(cq + 3) * YS + k);
        }
    }

    // ---- step count and t-mapping ----
    int nsteps, tbase;
    if (mode == 0) {
        nsteps = (c == 0) ? 64 : (c == CCH - 1 ? (64 + WU) : (64 + WU + 1));
        tbase  = (c == 0) ? 1 : (64 * c - WU);
    } else if (mode == 1) {
        nsteps = (c == CCH - 1) ? 64 : (c == 0 ? (64 + WU) : (64 + WU + 1));
        tbase  = (c == CCH - 1) ? 2046 : (64 * c + 63 + WU);
    } else {
        nsteps = TM1;
        tbase  = 1;
    }

    // ---- initial vector + exact boundary writes (raw, to scratch) ----
    if (tid < YS) {
        float v;
        if (mode == 0) {
            v = (c == 0) ? g_bx[tid] * pi[tid] : 1.0f;
            if (c == 0 && r == 0) g_alpha[tid] = v;
        } else if (mode == 1) {
            if (c == CCH - 1) {
                v = g_bx[(TS - 1) * YS + tid];
                if (r == 0) g_beta[(TS - 1) * YS + tid] = 1.0f;
            } else v = 1.0f;
        } else {
            v = g_bx[tid] * pi[tid];
        }
        s_buf[0][tid] = v;
    }
    __syncthreads();
    CLUSTER_ARRIVE();
    CLUSTER_WAIT();

    int tz = -1;
    int t = tbase;
    float4 bxv = __ldg((const float4*)&g_bx[t * YS + cq]);

    for (int s = 0; s < nsteps; ++s) {
        const int slot  = s % NSLOT;
        const int slot2 = (s + 1) % NSLOT;
        t = (mode == 1) ? (tbase - s) : (tbase + s);

        if (s > 0) {
            const unsigned int fa = flagu + (unsigned int)(slot * 64 + lane) * 4u;
            const unsigned int fb = fa + 32u * 4u;
            const unsigned int need = (unsigned int)s;
            bool ok = (ld_rlx(fa) >= need) && (ld_rlx(fb) >= need);
            while (!__all_sync(0xffffffffu, ok)) {
                __nanosleep(8);
                ok = (ld_rlx(fa) >= need) && (ld_rlx(fb) >= need);
            }
            ld_acq(fa);
        }

        // gather v (k = 16*j + ks); conflict-free (16 addrs, 2-lane broadcast)
        float vreg[16];
#pragma unroll
        for (int j = 0; j < 16; ++j) vreg[j] = s_buf[slot][16 * j + ks];

        if (mode == 2) {
            unsigned int orv = 0u;
#pragma unroll
            for (int j = 0; j < 16; ++j) orv |= __float_as_uint(vreg[j]);
            unsigned int o = __reduce_or_sync(0xffffffffu, orv);
            if (lane == 0) s_redu[w] = o;
            __syncthreads();
            if (tid == 0) {
                unsigned int oo = 0u;
                for (int i = 0; i < 16; ++i) oo |= s_redu[i];
                if (oo == 0u) s_dead = 1;
            }
            __syncthreads();
            if (s_dead) { tz = s; break; }
        }

        const unsigned int nbuf = bufu + (unsigned int)(slot2 * YS + cq) * 4u;
        const unsigned int nfl  = flagu + (unsigned int)(slot2 * 64 + (int)r * 32 + w * 2 + cg) * 4u;
        const unsigned int tag  = (unsigned int)(s + 1);
        const bool dopush = (mode == 2) || (s + 1 < nsteps);

        if (mode != 2) {
            float4 acc = make_float4(0.f, 0.f, 0.f, 0.f);
#pragma unroll
            for (int j = 0; j < 16; ++j) {
                float vv = vreg[j];
                acc.x = fmaf(vv, aq[j].x, acc.x);
                acc.y = fmaf(vv, aq[j].y, acc.y);
                acc.z = fmaf(vv, aq[j].z, acc.z);
                acc.w = fmaf(vv, aq[j].w, acc.w);
            }
#pragma unroll
            for (int off = 8; off > 0; off >>= 1) {
                acc.x += __shfl_xor_sync(0xffffffffu, acc.x, off);
                acc.y += __shfl_xor_sync(0xffffffffu, acc.y, off);
                acc.z += __shfl_xor_sync(0xffffffffu, acc.z, off);
                acc.w += __shfl_xor_sync(0xffffffffu, acc.w, off);
            }
            float4 p = make_float4(acc.x * bxv.x, acc.y * bxv.y,
                                   acc.z * bxv.z, acc.w * bxv.w);

            bool outr = (mode == 0)
                ? (c == 0 ? (s <= 62) : (s >= WU && s <= WU + 63))
                : (c == CCH - 1 ? (s <= 62) : (s >= WU && s <= WU + 63));
            if (outr && ks == 2) {
                if (mode == 0) *(float4*)&g_alpha[t * YS + cq] = p;
                else           *(float4*)&g_beta[t * YS + cq]  = acc;
            }
            if (dopush) {
                if (ks == 0) {                       // remote push + flag
                    push_quad(nbuf, r ^ 1u, p);
                    flag_release(nfl, r ^ 1u, tag);
                } else if (ks == 1) {                // own push + flag
                    push_quad(nbuf, r, p);
                    flag_release(nfl, r, tag);
                }
            }

            // ---- stitching sums ----
            float* dst = 0;
            if (mode == 0) {
                if (c >= 1 && s == WU) dst = &g_SfA[c][r];
                else if ((c == 0 && s == 63) || (c >= 1 && c <= CCH - 2 && s == WU + 64)) dst = &g_SoA[c][r];
                else if (c == CCH - 1 && s == WU + 63) dst = &g_SlA[r];
            } else {
                if (c <= CCH - 2 && s == WU) dst = &g_SfB[c][r];
                else if ((c == CCH - 1 && s == 63) || (c >= 1 && c <= CCH - 2 && s == WU + 64)) dst = &g_SoB[c][r];
            }
            if (dst) {
                if (ks == 2) {
                    float4 q = (mode == 0) ? p : acc;
                    s_redf[w * 2 + cg] = q.x + q.y + q.z + q.w;
                }
                __syncthreads();
                if (tid == 0) {
                    float ss = 0.f;
                    for (int i = 0; i < 32; ++i) ss += s_redf[i];
                    *dst = ss;
                }
            }
        } else {
            // ---- exact Viterbi step (bit-identical scores & tie semantics) ----
            unsigned int bu[4] = {0u, 0u, 0u, 0u};
            int bi[4] = {ks, ks, ks, ks};
#pragma unroll
            for (int j = 0; j < 16; ++j) {
                int k = 16 * j + ks;
                float vv = vreg[j];
                unsigned int s0 = __float_as_uint(fmul_ftz(vv, aq[j].x));
                unsigned int s1 = __float_as_uint(fmul_ftz(vv, aq[j].y));
                unsigned int s2 = __float_as_uint(fmul_ftz(vv, aq[j].z));
                unsigned int s3 = __float_as_uint(fmul_ftz(vv, aq[j].w));
                if (s0 > bu[0]) { bu[0] = s0; bi[0] = k; }
                if (s1 > bu[1]) { bu[1] = s1; bi[1] = k; }
                if (s2 > bu[2]) { bu[2] = s2; bi[2] = k; }
                if (s3 > bu[3]) { bu[3] = s3; bi[3] = k; }
            }
#pragma unroll
            for (int off = 8; off > 0; off >>= 1) {
#pragma unroll
                for (int jj = 0; jj < 4; ++jj) {
                    unsigned int ou = __shfl_xor_sync(0xffffffffu, bu[jj], off);
                    int oi = __shfl_xor_sync(0xffffffffu, bi[jj], off);
                    if (ou > bu[jj] || (ou == bu[jj] && oi < bi[jj])) { bu[jj] = ou; bi[jj] = oi; }
                }
            }
            float4 p;
            p.x = fmul_ftz(bxv.x, __uint_as_float(bu[0]));
            p.y = fmul_ftz(bxv.y, __uint_as_float(bu[1]));
            p.z = fmul_ftz(bxv.z, __uint_as_float(bu[2]));
            p.w = fmul_ftz(bxv.w, __uint_as_float(bu[3]));
            if (ks == 0) {
                push_quad(nbuf, r ^ 1u, p);
                flag_release(nfl, r ^ 1u, tag);
            } else if (ks == 1) {
                push_quad(nbuf, r, p);
                flag_release(nfl, r, tag);
            } else if (ks == 3) {
                unsigned int pk = (unsigned int)bi[0] | ((unsigned int)bi[1] << 8)
                                | ((unsigned int)bi[2] << 16) | ((unsigned int)bi[3] << 24);
                *(unsigned int*)(g_bp + (size_t)(t - 1) * YS + cq) = pk;
                if (t - 1 < 64)
                    push_u32(bpcu + (unsigned int)((t - 1) * YS + cq), 0u, pk);
            }
        }

        if (s + 1 < nsteps) {
            int tn = (mode == 1) ? (tbase - (s + 1)) : (tbase + (s + 1));
            bxv = __ldg((const float4*)&g_bx[tn * YS + cq]);
        }
    }

    // ---- Viterbi epilogue ----
    if (mode == 2) {
        if (tz >= 0) {
            unsigned int* bp32 = (unsigned int*)(g_bp + (size_t)tz * YS);
            int n32 = (TM1 - tz) * (YS / 4);
            for (int i = (int)r * 512 + tid; i < n32; i += 1024) bp32[i] = 0u;
        }
        CLUSTER_ARRIVE();   // orders remote s_bpc stores + zero-fill before backtrack
        CLUSTER_WAIT();
        if (r == 0) {
            if (tz >= 0) {
                for (int k = tz + tid; k < TS - 1; k += 512)
                    out[OFF_PATH + k] = 0.0f;
            } else if (w == 0) {
                const int fslot = TM1 % NSLOT;
                const unsigned int fa = flagu + (unsigned int)(fslot * 64 + lane) * 4u;
                const unsigned int fb = fa + 32u * 4u;
                bool ok = (ld_rlx(fa) >= (unsigned int)TM1) && (ld_rlx(fb) >= (unsigned int)TM1);
                while (!__all_sync(0xffffffffu, ok)) {
                    __nanosleep(8);
                    ok = (ld_rlx(fa) >= (unsigned int)TM1) && (ld_rlx(fb) >= (unsigned int)TM1);
                }
                ld_acq(fa);
                if (lane == 0) {
                    unsigned int m = __float_as_uint(s_buf[fslot][0]);
                    int idx = 0;
                    for (int i = 1; i < YS; ++i) {
                        unsigned int vi = __float_as_uint(s_buf[fslot][i]);
                        if (vi > m) { m = vi; idx = i; }
                    }
                    s_last = idx;
                }
            }
            __syncthreads();
            if (tid == 0) {
                int last = s_last;
                out[OFF_PATH + TS - 1] = (float)last;
                int st = last;
                int tstart = (tz >= 0) ? (tz - 1) : (TS - 2);
                for (int tt = tstart; tt >= 0; --tt) {
                    st = (tt < 64) ? (int)s_bpc[tt * YS + st]
                                   : (int)g_bp[(size_t)tt * YS + st];
                    out[OFF_PATH + tt] = (float)st;
                }
            }
        }
    }

    CLUSTER_ARRIVE();
    CLUSTER_WAIT();
}

// ---------------------------------------------------------------- stitch
__global__ void stitch_kernel(float* __restrict__ out) {
    __shared__ float sSoA[CCH], sSfA[CCH], sSoB[CCH], sSfB[CCH];
    int tid = threadIdx.x;  // 64 threads
    if (tid < CCH) {
        sSoA[tid] = g_SoA[tid][0] + g_SoA[tid][1];
        sSfA[tid] = g_SfA[tid][0] + g_SfA[tid][1];
    } else {
        int c = tid - CCH;
        sSoB[c] = g_SoB[c][0] + g_SoB[c][1];
        sSfB[c] = g_SfB[c][0] + g_SfB[c][1];
    }
    __syncthreads();
    if (tid == 0) {
        double k = 1.0;
        g_kap[0] = 1.0f;
        for (int c = 1; c < CCH; ++c) {
            k *= (double)sSoA[c - 1] / (double)sSfA[c];
            g_kap[c] = (float)k;
        }
        double p = k * (double)(g_SlA[0] + g_SlA[1]);
        g_p = (float)p;
        out[OFF_P] = (float)p;
    }
    if (tid == 32) {
        double l = 1.0;
        g_lam[CCH - 1] = 1.0f;
        for (int c = CCH - 2; c >= 0; --c) {
            l *= (double)sSoB[c + 1] / (double)sSfB[c];
            g_lam[c] = (float)l;
        }
    }
}

// ---------------------------------------------------------------- xi (fused)
#define XG 8
__global__ void xi_fused_kernel(const float* __restrict__ A, float* __restrict__ out) {
    __shared__ __align__(16) float s_a[YS];
    __shared__ __align__(16) float s_w[YS];
    __shared__ __align__(16) float s_x[XG][264];
    int t = blockIdx.x, tid = threadIdx.x;
    float ka  = g_kap[t >> 6];
    float la0 = g_lam[t >> 6];
    float la1 = g_lam[(t + 1) >> 6];

    float av = g_alpha[t * YS + tid] * ka;
    float b1 = g_beta[(t + 1) * YS + tid] * la1;
    float b0 = g_beta[t * YS + tid] * la0;
    s_a[tid] = av;
    s_w[tid] = g_bx[(t + 1) * YS + tid] * b1;
    out[OFF_ALPHA + t * YS + tid] = av;
    out[OFF_BETA + (t + 1) * YS + tid] = b1;
    out[OFF_GAMMA + t * YS + tid] = av * b0 / g_p;
    __syncthreads();

    float wj = s_w[tid];
    const float* Ac = A + tid;
    float* base = out + OFF_XI + (size_t)t * YS * YS;

    for (int g0 = 0; g0 < YS; g0 += XG) {
#pragma unroll
        for (int q = 0; q < XG; ++q) {
            int i = g0 + q;
            float a2 = __ldg(Ac + (size_t)i * YS);
            s_x[q][tid + 1] = (s_a[i] * a2) * wj;
        }
        __syncthreads();
#pragma unroll 2
        for (int u = tid; u < XG * 63; u += YS) {
            int row = u / 63, q = u - row * 63;
            float4 v = *(const float4*)&s_x[row][4 + 4 * q];
            *(float4*)(base + (size_t)(g0 + row) * YS + 3 + 4 * q) = v;
        }
        if (tid < XG * 4) {
            int row = tid >> 2, cc = tid & 3;
            int col = (cc < 3) ? cc : 255;
            base[(size_t)(g0 + row) * YS + col] = s_x[row][col + 1];
        }
        __syncthreads();
    }
}

// ---------------------------------------------------------------- tail
__global__ void tail_kernel(float* __restrict__ out) {
    int tid = threadIdx.x;
    float a  = g_alpha[(TS - 1) * YS + tid] * g_kap[CCH - 1];
    float bT = g_beta[(TS - 1) * YS + tid] * g_lam[CCH - 1];
    out[OFF_ALPHA + (TS - 1) * YS + tid] = a;
    out[OFF_BETA + tid] = g_beta[tid] * g_lam[0];
    out[OFF_GAMMA + (TS - 1) * YS + tid] = a * bT / g_p;
}

// ---------------------------------------------------------------- launch
extern "C" void kernel_launch(void* const* d_in, const int* in_sizes, int n_in,
                              void* d_out, int out_size) {
    const int*   x  = (const int*)d_in[0];
    const float* A  = (const float*)d_in[1];
    const float* b  = (const float*)d_in[2];
    const float* pi = (const float*)d_in[3];
    float* out = (float*)d_out;

    prep_bx_kernel<<<TS, YS>>>(x, b);
    dummy_kernel<<<1, 32>>>();
    dummy_kernel<<<1, 32>>>();
    chunk_kernel<<<2 * (1 + 2 * CCH), 512>>>(A, pi, out);   // 4th launch -> ncu
    stitch_kernel<<<1, 64>>>(out);
    xi_fused_kernel<<<TM1, YS>>>(A, out);
    tail_kernel<<<1, YS>>>(out);
}